// round 17
// baseline (speedup 1.0000x reference)
#include <cuda_runtime.h>
#include <cuda_fp16.h>
#include <math.h>

#define NN 50000
#define NE 800000
#define NET (NE + NN)       // edges + self loops = 850000
#define HC 256              // H*C
#define NH 4
#define CC 64
#define NB_SCAN 196         // ceil(NN/256)

// ---------------- scratch (static device globals; no allocs) ----------------
__device__ __align__(16) __half g_h[NN * HC];     // transformed features (fp16, per layer)
__device__ __align__(16) __half g_x1[NN * HC];    // layer-0 activated output (fp16)
__device__ __align__(16) __half g_acc[NN * HC];   // layer-1 aggregation output (fp16)
__device__ __align__(16) float g_asrc[NN * NH];
__device__ __align__(16) float g_adst[NN * NH];
__device__ int g_deg[NN];
__device__ int g_off[NN + 1];
__device__ int g_cur[NN];
__device__ int g_adj[NET];                        // src ids grouped by dst
__device__ int g_is64;

// ---------------- zero deg (=1: self-loop pre-counted) + detect dtype ----------------
__global__ void zerodetect_k(const int* ei32) {
    int i = blockIdx.x * blockDim.x + threadIdx.x;
    if (i < NN) g_deg[i] = 1;
    if (i == 0) {
        int ok = 1;
        #pragma unroll
        for (int k = 0; k < 64; k++)
            if (ei32[2 * k + 1] != 0) ok = 0;
        g_is64 = ok;
    }
}

// ---------------- CSR build (real edges only; self-loops planted by scanfused) ----------------
__global__ void hist_k(const void* __restrict__ ei) {
    int q = blockIdx.x * blockDim.x + threadIdx.x;
    int e = q * 4;
    if (e >= NE) return;
    int d0, d1, d2, d3;
    if (g_is64) {
        const longlong2* p = (const longlong2*)((const long long*)ei + NE);
        longlong2 a = p[q * 2];
        longlong2 b = p[q * 2 + 1];
        d0 = (int)a.x; d1 = (int)a.y; d2 = (int)b.x; d3 = (int)b.y;
    } else {
        int4 a = ((const int4*)((const int*)ei + NE))[q];
        d0 = a.x; d1 = a.y; d2 = a.z; d3 = a.w;
    }
    atomicAdd(&g_deg[d0], 1);
    atomicAdd(&g_deg[d1], 1);
    atomicAdd(&g_deg[d2], 1);
    atomicAdd(&g_deg[d3], 1);
}

// fused scan: each block computes its own base by reducing deg[0..blockIdx*256),
// then does the per-block exclusive scan, writes off/cur and plants the self-loop.
__global__ void scanfused_k() {
    __shared__ int sh[256];
    __shared__ int base;
    const int t = threadIdx.x;
    const int lim = blockIdx.x * 256;

    // phase 1: base = sum of deg[0 .. lim)  (coalesced strided reduce)
    int tot = 0;
    for (int j = t; j < lim; j += 256) tot += __ldg(&g_deg[j]);
    sh[t] = tot; __syncthreads();
    for (int o = 128; o; o >>= 1) {
        if (t < o) sh[t] += sh[t + o];
        __syncthreads();
    }
    if (t == 0) base = sh[0];
    __syncthreads();

    // phase 2: per-block inclusive scan of deg
    int i = lim + t;
    int d = (i < NN) ? g_deg[i] : 0;
    sh[t] = d; __syncthreads();
    for (int o = 1; o < 256; o <<= 1) {
        int x = (t >= o) ? sh[t - o] : 0;
        __syncthreads();
        sh[t] += x;
        __syncthreads();
    }
    if (i < NN) {
        int off = base + sh[t] - d;
        g_off[i] = off;
        g_adj[off] = i;          // plant self-loop in first slot
        g_cur[i] = off + 1;      // real edges fill after it
        if (i == NN - 1) g_off[NN] = off + d;
    }
}

// fill real edges, 4 per thread (vectorized)
__global__ void fill_k(const void* __restrict__ ei) {
    int q = blockIdx.x * blockDim.x + threadIdx.x;
    int e = q * 4;
    if (e >= NE) return;
    int s0, s1, s2, s3, d0, d1, d2, d3;
    if (g_is64) {
        const long long* p = (const long long*)ei;
        longlong2 sa = ((const longlong2*)p)[q * 2];
        longlong2 sb = ((const longlong2*)p)[q * 2 + 1];
        longlong2 da = ((const longlong2*)(p + NE))[q * 2];
        longlong2 db = ((const longlong2*)(p + NE))[q * 2 + 1];
        s0 = (int)sa.x; s1 = (int)sa.y; s2 = (int)sb.x; s3 = (int)sb.y;
        d0 = (int)da.x; d1 = (int)da.y; d2 = (int)db.x; d3 = (int)db.y;
    } else {
        const int* p = (const int*)ei;
        int4 sv = ((const int4*)p)[q];
        int4 dv = ((const int4*)(p + NE))[q];
        s0 = sv.x; s1 = sv.y; s2 = sv.z; s3 = sv.w;
        d0 = dv.x; d1 = dv.y; d2 = dv.z; d3 = dv.w;
    }
    int p0 = atomicAdd(&g_cur[d0], 1);
    g_adj[p0] = s0;
    int p1 = atomicAdd(&g_cur[d1], 1);
    g_adj[p1] = s1;
    int p2 = atomicAdd(&g_cur[d2], 1);
    g_adj[p2] = s2;
    int p3 = atomicAdd(&g_cur[d3], 1);
    g_adj[p3] = s3;
}

// ---------------- tensor-core GEMM (fp16 HMMA, fp32 accum) ----------------
// ALPHA: fp16 output + per-row alpha dots (head = blockIdx.x).
// FMAX:  A-element = max(A, A2 + ab), A2 fp16; fp32 output with +bias.
// AHALF: A operand is fp16 in global memory.
#define APAD 40
#define BPAD 72
__device__ __forceinline__ unsigned su32(const void* p) {
    return (unsigned)__cvta_generic_to_shared(p);
}
__device__ __forceinline__ void ldm_x4(unsigned addr, unsigned& r0, unsigned& r1,
                                       unsigned& r2, unsigned& r3) {
    asm volatile("ldmatrix.sync.aligned.m8n8.x4.shared.b16 {%0,%1,%2,%3},[%4];"
                 : "=r"(r0), "=r"(r1), "=r"(r2), "=r"(r3) : "r"(addr));
}
__device__ __forceinline__ void ldm_x4t(unsigned addr, unsigned& r0, unsigned& r1,
                                        unsigned& r2, unsigned& r3) {
    asm volatile("ldmatrix.sync.aligned.m8n8.x4.trans.shared.b16 {%0,%1,%2,%3},[%4];"
                 : "=r"(r0), "=r"(r1), "=r"(r2), "=r"(r3) : "r"(addr));
}
__device__ __forceinline__ void mma16816(float& d0, float& d1, float& d2, float& d3,
                                         unsigned a0, unsigned a1, unsigned a2, unsigned a3,
                                         unsigned b0, unsigned b1) {
    asm volatile(
        "mma.sync.aligned.m16n8k16.row.col.f32.f16.f16.f32 "
        "{%0,%1,%2,%3},{%4,%5,%6,%7},{%8,%9},{%0,%1,%2,%3};"
        : "+f"(d0), "+f"(d1), "+f"(d2), "+f"(d3)
        : "r"(a0), "r"(a1), "r"(a2), "r"(a3), "r"(b0), "r"(b1));
}

template <bool ALPHA, bool FMAX, bool AHALF>
__global__ __launch_bounds__(256) void gemm16_k(
    const void* __restrict__ Av, const void* __restrict__ A2v,
    const float* __restrict__ ab, const float* __restrict__ B,
    const float* __restrict__ bias,
    const float* __restrict__ aS, const float* __restrict__ aD,
    void* __restrict__ Cv, int M, int K, int Nc)
{
    __shared__ __half As[128][APAD];
    __shared__ __half Bs[32][BPAD];
    __shared__ float sPs[128];
    __shared__ float sPd[128];

    const int tid = threadIdx.x;
    const int lane = tid & 31;
    const int warp = tid >> 5;
    const int wm = warp & 3;
    const int wn = warp >> 2;
    const int m0 = blockIdx.y * 128;
    const int n0 = blockIdx.x * 64;

    float acc[2][4][4];
    #pragma unroll
    for (int mt = 0; mt < 2; mt++)
        #pragma unroll
        for (int nt = 0; nt < 4; nt++)
            #pragma unroll
            for (int r = 0; r < 4; r++) acc[mt][nt][r] = 0.f;

    if (ALPHA && tid < 128) { sPs[tid] = 0.f; sPd[tid] = 0.f; }

    float4 ra[4], ran[4];
    uint4 ra16[2], ran16[2];
    float4 rb[2], rbn[2];

    auto load_fragA = [&](int kt, float4 (&la)[4], uint4 (&la16)[2]) {
        if (AHALF) {
            const __half* Ah = (const __half*)Av;
            #pragma unroll
            for (int i = 0; i < 2; i++) {
                int q = tid + i * 256;
                int row = q >> 2;
                int ks = (q & 3) * 8;
                uint4 v = make_uint4(0, 0, 0, 0);
                if (m0 + row < M) {
                    v = *(const uint4*)(Ah + (size_t)(m0 + row) * K + kt + ks);
                    if (FMAX) {
                        const __half* a2p = (const __half*)A2v + (size_t)(m0 + row) * K + kt + ks;
                        uint4 v2 = *(const uint4*)a2p;
                        float4 b20 = *(const float4*)(ab + kt + ks);
                        float4 b21 = *(const float4*)(ab + kt + ks + 4);
                        float2 x0 = __half22float2(*(__half2*)&v.x);
                        float2 x1 = __half22float2(*(__half2*)&v.y);
                        float2 x2 = __half22float2(*(__half2*)&v.z);
                        float2 x3 = __half22float2(*(__half2*)&v.w);
                        float2 y0 = __half22float2(*(__half2*)&v2.x);
                        float2 y1 = __half22float2(*(__half2*)&v2.y);
                        float2 y2 = __half22float2(*(__half2*)&v2.z);
                        float2 y3 = __half22float2(*(__half2*)&v2.w);
                        __half2 h0 = __floats2half2_rn(fmaxf(x0.x, y0.x + b20.x),
                                                       fmaxf(x0.y, y0.y + b20.y));
                        __half2 h1 = __floats2half2_rn(fmaxf(x1.x, y1.x + b20.z),
                                                       fmaxf(x1.y, y1.y + b20.w));
                        __half2 h2 = __floats2half2_rn(fmaxf(x2.x, y2.x + b21.x),
                                                       fmaxf(x2.y, y2.y + b21.y));
                        __half2 h3 = __floats2half2_rn(fmaxf(x3.x, y3.x + b21.z),
                                                       fmaxf(x3.y, y3.y + b21.w));
                        v.x = *(unsigned*)&h0;
                        v.y = *(unsigned*)&h1;
                        v.z = *(unsigned*)&h2;
                        v.w = *(unsigned*)&h3;
                    }
                }
                la16[i] = v;
            }
        } else {
            const float* A = (const float*)Av;
            #pragma unroll
            for (int i = 0; i < 4; i++) {
                int q = tid + i * 256;
                int row = q >> 3;
                int ks = (q & 7) * 4;
                float4 v = make_float4(0.f, 0.f, 0.f, 0.f);
                if (m0 + row < M)
                    v = *(const float4*)(A + (size_t)(m0 + row) * K + kt + ks);
                la[i] = v;
            }
        }
    };
    auto load_fragB = [&](int kt, float4 (&lb)[2]) {
        #pragma unroll
        for (int i = 0; i < 2; i++) {
            int q = tid + i * 256;
            int kr = q >> 4;
            int ns = (q & 15) * 4;
            lb[i] = *(const float4*)(B + (size_t)(kt + kr) * Nc + n0 + ns);
        }
    };
    auto store_frag = [&](const float4 (&la)[4], const uint4 (&la16)[2],
                          const float4 (&lb)[2]) {
        if (AHALF) {
            #pragma unroll
            for (int i = 0; i < 2; i++) {
                int q = tid + i * 256;
                int row = q >> 2;
                int ks = (q & 3) * 8;
                *(uint4*)&As[row][ks] = la16[i];
            }
        } else {
            #pragma unroll
            for (int i = 0; i < 4; i++) {
                int q = tid + i * 256;
                int row = q >> 3;
                int ks = (q & 7) * 4;
                *(__half2*)&As[row][ks]     = __floats2half2_rn(la[i].x, la[i].y);
                *(__half2*)&As[row][ks + 2] = __floats2half2_rn(la[i].z, la[i].w);
            }
        }
        #pragma unroll
        for (int i = 0; i < 2; i++) {
            int q = tid + i * 256;
            int kr = q >> 4;
            int ns = (q & 15) * 4;
            *(__half2*)&Bs[kr][ns]     = __floats2half2_rn(lb[i].x, lb[i].y);
            *(__half2*)&Bs[kr][ns + 2] = __floats2half2_rn(lb[i].z, lb[i].w);
        }
    };

    load_fragA(0, ra, ra16);
    load_fragB(0, rb);

    for (int kt = 0; kt < K; kt += 32) {
        store_frag(ra, ra16, rb);
        __syncthreads();

        if (kt + 32 < K) {
            load_fragA(kt + 32, ran, ran16);
            load_fragB(kt + 32, rbn);
        }

        #pragma unroll
        for (int kg = 0; kg < 2; kg++) {
            unsigned a[2][4], bq[2][4];
            #pragma unroll
            for (int mt = 0; mt < 2; mt++) {
                unsigned ad = su32(&As[wm * 32 + mt * 16 + (lane & 15)]
                                      [kg * 16 + (lane >> 4) * 8]);
                ldm_x4(ad, a[mt][0], a[mt][1], a[mt][2], a[mt][3]);
            }
            #pragma unroll
            for (int np = 0; np < 2; np++) {
                unsigned bd = su32(&Bs[kg * 16 + (lane & 15)]
                                      [wn * 32 + np * 16 + (lane >> 4) * 8]);
                ldm_x4t(bd, bq[np][0], bq[np][1], bq[np][2], bq[np][3]);
            }
            #pragma unroll
            for (int mt = 0; mt < 2; mt++)
                #pragma unroll
                for (int nt = 0; nt < 4; nt++) {
                    unsigned b0 = bq[nt >> 1][(nt & 1) * 2];
                    unsigned b1 = bq[nt >> 1][(nt & 1) * 2 + 1];
                    mma16816(acc[mt][nt][0], acc[mt][nt][1],
                             acc[mt][nt][2], acc[mt][nt][3],
                             a[mt][0], a[mt][1], a[mt][2], a[mt][3], b0, b1);
                }
        }
        __syncthreads();

        #pragma unroll
        for (int i = 0; i < 4; i++) ra[i] = ran[i];
        #pragma unroll
        for (int i = 0; i < 2; i++) { ra16[i] = ran16[i]; rb[i] = rbn[i]; }
    }

    #pragma unroll
    for (int mt = 0; mt < 2; mt++) {
        int row0 = m0 + wm * 32 + mt * 16 + (lane >> 2);
        #pragma unroll
        for (int nt = 0; nt < 4; nt++) {
            int col = n0 + wn * 32 + nt * 8 + 2 * (lane & 3);
            if (ALPHA) {
                __half* C = (__half*)Cv;
                if (row0 < M)
                    *(__half2*)(C + (size_t)row0 * Nc + col) =
                        __floats2half2_rn(acc[mt][nt][0], acc[mt][nt][1]);
                if (row0 + 8 < M)
                    *(__half2*)(C + (size_t)(row0 + 8) * Nc + col) =
                        __floats2half2_rn(acc[mt][nt][2], acc[mt][nt][3]);
            } else {
                float* C = (float*)Cv;
                float2 bv = *(const float2*)(bias + col);
                if (row0 < M) {
                    float2 v = make_float2(acc[mt][nt][0] + bv.x, acc[mt][nt][1] + bv.y);
                    *(float2*)(C + (size_t)row0 * Nc + col) = v;
                }
                if (row0 + 8 < M) {
                    float2 v = make_float2(acc[mt][nt][2] + bv.x, acc[mt][nt][3] + bv.y);
                    *(float2*)(C + (size_t)(row0 + 8) * Nc + col) = v;
                }
            }
        }
    }

    if (ALPHA) {
        #pragma unroll
        for (int mt = 0; mt < 2; mt++) {
            float psg = 0.f, psg8 = 0.f, pdg = 0.f, pdg8 = 0.f;
            #pragma unroll
            for (int nt = 0; nt < 4; nt++) {
                int col = n0 + wn * 32 + nt * 8 + 2 * (lane & 3);
                float2 sv = *(const float2*)(aS + col);
                float2 dv = *(const float2*)(aD + col);
                psg  += acc[mt][nt][0] * sv.x + acc[mt][nt][1] * sv.y;
                psg8 += acc[mt][nt][2] * sv.x + acc[mt][nt][3] * sv.y;
                pdg  += acc[mt][nt][0] * dv.x + acc[mt][nt][1] * dv.y;
                pdg8 += acc[mt][nt][2] * dv.x + acc[mt][nt][3] * dv.y;
            }
            #pragma unroll
            for (int o = 1; o <= 2; o <<= 1) {
                psg  += __shfl_xor_sync(0xffffffffu, psg, o);
                psg8 += __shfl_xor_sync(0xffffffffu, psg8, o);
                pdg  += __shfl_xor_sync(0xffffffffu, pdg, o);
                pdg8 += __shfl_xor_sync(0xffffffffu, pdg8, o);
            }
            if ((lane & 3) == 0) {
                int rl = wm * 32 + mt * 16 + (lane >> 2);
                atomicAdd(&sPs[rl], psg);
                atomicAdd(&sPs[rl + 8], psg8);
                atomicAdd(&sPd[rl], pdg);
                atomicAdd(&sPd[rl + 8], pdg8);
            }
        }
        __syncthreads();
        if (tid < 128) {
            int row = m0 + tid;
            if (row < M) {
                int head = blockIdx.x;
                g_asrc[row * 4 + head] = sPs[tid];
                g_adst[row * 4 + head] = sPd[tid];
            }
        }
    }
}

// ---------------- fused edge-softmax + CSR gather (fp16 features, fp16 out) ----------------
// 32 threads per node, 8 nodes per block, 4x unrolled, __ldcg.
// ACT=true: bias + BN(eval) + ELU epilogue. Output always fp16.
template <bool ACT>
__global__ __launch_bounds__(256) void gather_k(
    const __half* __restrict__ h, __half* __restrict__ outh,
    const float* __restrict__ b0,
    const float* __restrict__ gamma,
    const float* __restrict__ beta)
{
    int node = blockIdx.x * 8 + (threadIdx.x >> 5);
    if (node >= NN) return;
    int t = threadIdx.x & 31;
    int head = t >> 3;
    int oct = t & 7;
    int p = g_off[node];
    const int end = g_off[node + 1];

    const float ad = g_adst[node * 4 + head];
    float a[8];
    #pragma unroll
    for (int i = 0; i < 8; i++) a[i] = 0.f;
    float wsum = 0.f;

    const int coff = head * 64 + oct * 8;

    for (; p + 4 <= end; p += 4) {
        int s0 = g_adj[p + 0];
        int s1 = g_adj[p + 1];
        int s2 = g_adj[p + 2];
        int s3 = g_adj[p + 3];
        float e0 = g_asrc[s0 * 4 + head] + ad;
        float e1 = g_asrc[s1 * 4 + head] + ad;
        float e2 = g_asrc[s2 * 4 + head] + ad;
        float e3 = g_asrc[s3 * 4 + head] + ad;
        uint4 r0 = __ldcg((const uint4*)(h + (size_t)s0 * HC + coff));
        uint4 r1 = __ldcg((const uint4*)(h + (size_t)s1 * HC + coff));
        uint4 r2 = __ldcg((const uint4*)(h + (size_t)s2 * HC + coff));
        uint4 r3 = __ldcg((const uint4*)(h + (size_t)s3 * HC + coff));
        e0 = e0 > 0.f ? e0 : 0.2f * e0;
        e1 = e1 > 0.f ? e1 : 0.2f * e1;
        e2 = e2 > 0.f ? e2 : 0.2f * e2;
        e3 = e3 > 0.f ? e3 : 0.2f * e3;
        float w0 = __expf(e0), w1 = __expf(e1), w2 = __expf(e2), w3 = __expf(e3);
        wsum += (w0 + w1) + (w2 + w3);
        const uint4* rr[4] = {&r0, &r1, &r2, &r3};
        float ww[4] = {w0, w1, w2, w3};
        #pragma unroll
        for (int u = 0; u < 4; u++) {
            float2 f0 = __half22float2(*(const __half2*)&rr[u]->x);
            float2 f1 = __half22float2(*(const __half2*)&rr[u]->y);
            float2 f2 = __half22float2(*(const __half2*)&rr[u]->z);
            float2 f3 = __half22float2(*(const __half2*)&rr[u]->w);
            float w = ww[u];
            a[0] = fmaf(w, f0.x, a[0]);
            a[1] = fmaf(w, f0.y, a[1]);
            a[2] = fmaf(w, f1.x, a[2]);
            a[3] = fmaf(w, f1.y, a[3]);
            a[4] = fmaf(w, f2.x, a[4]);
            a[5] = fmaf(w, f2.y, a[5]);
            a[6] = fmaf(w, f3.x, a[6]);
            a[7] = fmaf(w, f3.y, a[7]);
        }
    }
    for (; p < end; p++) {
        int s = g_adj[p];
        float e = g_asrc[s * 4 + head] + ad;
        e = e > 0.f ? e : 0.2f * e;
        float w = __expf(e);
        uint4 raw = __ldcg((const uint4*)(h + (size_t)s * HC + coff));
        float2 f0 = __half22float2(*(__half2*)&raw.x);
        float2 f1 = __half22float2(*(__half2*)&raw.y);
        float2 f2 = __half22float2(*(__half2*)&raw.z);
        float2 f3 = __half22float2(*(__half2*)&raw.w);
        a[0] = fmaf(w, f0.x, a[0]);
        a[1] = fmaf(w, f0.y, a[1]);
        a[2] = fmaf(w, f1.x, a[2]);
        a[3] = fmaf(w, f1.y, a[3]);
        a[4] = fmaf(w, f2.x, a[4]);
        a[5] = fmaf(w, f2.y, a[5]);
        a[6] = fmaf(w, f3.x, a[6]);
        a[7] = fmaf(w, f3.y, a[7]);
        wsum += w;
    }

    float inv = 1.0f / (wsum + 1e-16f);
    #pragma unroll
    for (int i = 0; i < 8; i++) a[i] *= inv;

    if (ACT) {
        const float r = rsqrtf(1.0f + 1e-5f);
        #pragma unroll
        for (int u = 0; u < 2; u++) {
            float4 bb = *(const float4*)(b0 + coff + u * 4);
            float4 gg = *(const float4*)(gamma + coff + u * 4);
            float4 be = *(const float4*)(beta + coff + u * 4);
            float v0 = (a[u * 4 + 0] + bb.x) * (gg.x * r) + be.x;
            float v1 = (a[u * 4 + 1] + bb.y) * (gg.y * r) + be.y;
            float v2 = (a[u * 4 + 2] + bb.z) * (gg.z * r) + be.z;
            float v3 = (a[u * 4 + 3] + bb.w) * (gg.w * r) + be.w;
            a[u * 4 + 0] = v0 > 0.f ? v0 : expm1f(v0);
            a[u * 4 + 1] = v1 > 0.f ? v1 : expm1f(v1);
            a[u * 4 + 2] = v2 > 0.f ? v2 : expm1f(v2);
            a[u * 4 + 3] = v3 > 0.f ? v3 : expm1f(v3);
        }
    }
    __half2 h0 = __floats2half2_rn(a[0], a[1]);
    __half2 h1 = __floats2half2_rn(a[2], a[3]);
    __half2 h2 = __floats2half2_rn(a[4], a[5]);
    __half2 h3 = __floats2half2_rn(a[6], a[7]);
    uint4 pk;
    pk.x = *(unsigned*)&h0;
    pk.y = *(unsigned*)&h1;
    pk.z = *(unsigned*)&h2;
    pk.w = *(unsigned*)&h3;
    *(uint4*)(outh + (size_t)node * HC + coff) = pk;
}

// ---------------- launch ----------------
extern "C" void kernel_launch(void* const* d_in, const int* in_sizes, int n_in,
                              void* d_out, int out_size)
{
    const float* x      = (const float*)d_in[0];
    const void*  ei     = d_in[1];
    const float* W0     = (const float*)d_in[2];
    const float* as0    = (const float*)d_in[3];
    const float* ad0    = (const float*)d_in[4];
    const float* b0     = (const float*)d_in[5];
    const float* gamma0 = (const float*)d_in[6];
    const float* beta0  = (const float*)d_in[7];
    const float* W1     = (const float*)d_in[8];
    const float* as1    = (const float*)d_in[9];
    const float* ad1    = (const float*)d_in[10];
    const float* b1     = (const float*)d_in[11];
    const float* Wf     = (const float*)d_in[12];
    const float* bf     = (const float*)d_in[13];
    float* out = (float*)d_out;

    __half *h, *x1, *acc;
    cudaGetSymbolAddress((void**)&h,   g_h);
    cudaGetSymbolAddress((void**)&x1,  g_x1);
    cudaGetSymbolAddress((void**)&acc, g_acc);

    static cudaStream_t s2 = nullptr;
    static cudaEvent_t evFork = nullptr, evJoin = nullptr;
    if (s2 == nullptr) {
        cudaStreamCreateWithFlags(&s2, cudaStreamNonBlocking);
        cudaEventCreateWithFlags(&evFork, cudaEventDisableTiming);
        cudaEventCreateWithFlags(&evJoin, cudaEventDisableTiming);
    }

    const int mb = (NN + 127) / 128;
    const int gb = (NN + 7) / 8;
    const int hb = (NE / 4 + 255) / 256;   // hist: 4 edges/thread
    const int fb = (NE / 4 + 255) / 256;   // fill: 4 edges/thread

    // ---- fork: CSR build on s2 (4-kernel chain), concurrent with GEMM0 ----
    cudaEventRecord(evFork, 0);
    cudaStreamWaitEvent(s2, evFork, 0);

    zerodetect_k<<<(NN + 255) / 256, 256, 0, s2>>>((const int*)ei);
    hist_k<<<hb, 256, 0, s2>>>(ei);
    scanfused_k<<<NB_SCAN, 256, 0, s2>>>();
    fill_k<<<fb, 256, 0, s2>>>(ei);
    cudaEventRecord(evJoin, s2);

    gemm16_k<true, false, false><<<dim3(HC / 64, mb), 256>>>(
        x, nullptr, nullptr, W0, nullptr, as0, ad0, h, NN, 128, HC);

    cudaStreamWaitEvent(0, evJoin, 0);

    gather_k<true><<<gb, 256>>>(h, x1, b0, gamma0, beta0);

    // ---- layer 1 (A = x1 fp16) ----
    gemm16_k<true, false, true><<<dim3(HC / 64, mb), 256>>>(
        x1, nullptr, nullptr, W1, nullptr, as1, ad1, h, NN, HC, HC);
    gather_k<false><<<gb, 256>>>(h, acc, nullptr, nullptr, nullptr);

    // ---- JK-max + final projection: out = max(x1, acc + b1) @ Wf + bf ----
    gemm16_k<false, true, true><<<dim3(1, mb), 256>>>(
        x1, acc, b1, Wf, bf, nullptr, nullptr, out, NN, HC, 64);
}